// round 1
// baseline (speedup 1.0000x reference)
#include <cuda_runtime.h>

#define BATCH   262144
#define IN_DIM  768
#define OUT_DIM 32
#define QDEPTH  6

// Scratch (allocation-free: __device__ globals)
__device__ float  g_M[16][16];   // fixed-circuit matrix: final = M @ s
__device__ float4 g_h[BATCH];    // per-sample angles theta_w (w=0..3)

// ---------------------------------------------------------------------------
// Setup: compose the fixed part of the circuit (CNOT chains + RY(q_weights))
// into a single 16x16 matrix. Thread j builds column j independently.
// Index convention (matches JAX ref): i = q0*8 + q1*4 + q2*2 + q3,
// qubit w <-> bit (3-w).
// ---------------------------------------------------------------------------
__global__ void setup_kernel(const float* __restrict__ qw) {
    int j = threadIdx.x;
    if (j >= 16) return;
    float v[16];
#pragma unroll
    for (int i = 0; i < 16; i++) v[i] = (i == j) ? 1.0f : 0.0f;

    const int cm[3] = {8, 2, 4};  // controls: CNOT(0,1), CNOT(2,3), CNOT(1,2)
    const int tm[3] = {4, 1, 2};  // targets

    for (int k = 0; k < QDEPTH; k++) {
        // CNOT layer(s): amplitude permutation (swap rows where control set)
        for (int g = 0; g < 3; g++) {
            int cmask = cm[g], tmask = tm[g];
            for (int i = 0; i < 16; i++) {
                if ((i & cmask) && !(i & tmask)) {
                    float t = v[i]; v[i] = v[i | tmask]; v[i | tmask] = t;
                }
            }
        }
        // RY layer
        for (int w = 0; w < 4; w++) {
            int mask = 8 >> w;
            float half = 0.5f * qw[k * 4 + w];
            float c = cosf(half), s = sinf(half);
            for (int i = 0; i < 16; i++) {
                if (!(i & mask)) {
                    float a0 = v[i], a1 = v[i | mask];
                    v[i]        = c * a0 - s * a1;
                    v[i | mask] = s * a0 + c * a1;
                }
            }
        }
    }
    for (int i = 0; i < 16; i++) g_M[i][j] = v[i];
}

// ---------------------------------------------------------------------------
// Angle kernel: warp-per-sample 768->4 GEMV. Fully coalesced LDG.32,
// conflict-free LDS.128 of W1 (one float4 per input feature), butterfly sum.
// ---------------------------------------------------------------------------
__global__ __launch_bounds__(256) void angle_kernel(
    const float* __restrict__ inp,
    const float4* __restrict__ w1v,   // W1 as [768] float4 (row-major [768,4])
    const float* __restrict__ b1)
{
    __shared__ float4 sw[IN_DIM];
    __shared__ float  sb1[4];
    for (int i = threadIdx.x; i < IN_DIM; i += 256) sw[i] = w1v[i];
    if (threadIdx.x < 4) sb1[threadIdx.x] = b1[threadIdx.x];
    __syncthreads();

    int lane = threadIdx.x & 31;
    int b    = blockIdx.x * 8 + (threadIdx.x >> 5);

    const float* row = inp + (size_t)b * IN_DIM;
    float a0 = 0.f, a1 = 0.f, a2 = 0.f, a3 = 0.f;
#pragma unroll
    for (int j = 0; j < IN_DIM / 32; j++) {
        float  x = row[lane + 32 * j];
        float4 w = sw[lane + 32 * j];
        a0 = fmaf(x, w.x, a0);
        a1 = fmaf(x, w.y, a1);
        a2 = fmaf(x, w.z, a2);
        a3 = fmaf(x, w.w, a3);
    }
#pragma unroll
    for (int off = 16; off; off >>= 1) {
        a0 += __shfl_xor_sync(0xffffffffu, a0, off);
        a1 += __shfl_xor_sync(0xffffffffu, a1, off);
        a2 += __shfl_xor_sync(0xffffffffu, a2, off);
        a3 += __shfl_xor_sync(0xffffffffu, a3, off);
    }
    if (lane < 4) {
        float d = (lane == 0) ? a0 : (lane == 1) ? a1 : (lane == 2) ? a2 : a3;
        const float PI4 = 0.78539816339744830962f;
        float th = tanhf(d + sb1[lane]) * PI4 + PI4;  // x/2 + pi/4
        ((float*)g_h)[4 * b + lane] = th;
    }
}

// ---------------------------------------------------------------------------
// Tail kernel: per-sample state build, t = M s, p = t^2, signed sums -> q,
// out = q @ W2 + b2. All constants in shared (broadcast reads).
// ---------------------------------------------------------------------------
__global__ __launch_bounds__(256) void tail_kernel(
    const float4* __restrict__ w2v,   // W2 [4][32] -> 32 float4
    const float4* __restrict__ b2v,   // b2 [32]    -> 8 float4
    float4* __restrict__ out)
{
    __shared__ float4 sM[64];
    __shared__ float4 sW2[32];
    __shared__ float4 sb2[8];
    if (threadIdx.x < 64) sM[threadIdx.x]  = ((const float4*)g_M)[threadIdx.x];
    if (threadIdx.x < 32) sW2[threadIdx.x] = w2v[threadIdx.x];
    if (threadIdx.x < 8)  sb2[threadIdx.x] = b2v[threadIdx.x];
    __syncthreads();

    int b = blockIdx.x * 256 + threadIdx.x;
    float4 h = g_h[b];

    float s0, c0, s1, c1, s2, c2, s3, c3;
    __sincosf(h.x, &s0, &c0);
    __sincosf(h.y, &s1, &c1);
    __sincosf(h.z, &s2, &c2);
    __sincosf(h.w, &s3, &c3);

    float A[4]  = {c0 * c1, c0 * s1, s0 * c1, s0 * s1};  // qubits 0,1
    float Bq[4] = {c2 * c3, c2 * s3, s2 * c3, s2 * s3};  // qubits 2,3
    float sv[16];
#pragma unroll
    for (int i = 0; i < 16; i++) sv[i] = A[i >> 2] * Bq[i & 3];

    float q0 = 0.f, q1 = 0.f, q2 = 0.f, q3 = 0.f;
#pragma unroll
    for (int i = 0; i < 16; i++) {
        float4 m0 = sM[4 * i + 0], m1 = sM[4 * i + 1];
        float4 m2 = sM[4 * i + 2], m3 = sM[4 * i + 3];
        float t = m0.x * sv[0]  + m0.y * sv[1]  + m0.z * sv[2]  + m0.w * sv[3]
                + m1.x * sv[4]  + m1.y * sv[5]  + m1.z * sv[6]  + m1.w * sv[7]
                + m2.x * sv[8]  + m2.y * sv[9]  + m2.z * sv[10] + m2.w * sv[11]
                + m3.x * sv[12] + m3.y * sv[13] + m3.z * sv[14] + m3.w * sv[15];
        float p = t * t;
        q0 += (i & 8) ? -p : p;
        q1 += (i & 4) ? -p : p;
        q2 += (i & 2) ? -p : p;
        q3 += (i & 1) ? -p : p;
    }

    float4* o = out + (size_t)b * 8;
#pragma unroll
    for (int j = 0; j < 8; j++) {
        float4 w0 = sW2[j], w1 = sW2[8 + j], w2 = sW2[16 + j], w3 = sW2[24 + j];
        float4 bb = sb2[j];
        float4 r;
        r.x = bb.x + q0 * w0.x + q1 * w1.x + q2 * w2.x + q3 * w3.x;
        r.y = bb.y + q0 * w0.y + q1 * w1.y + q2 * w2.y + q3 * w3.y;
        r.z = bb.z + q0 * w0.z + q1 * w1.z + q2 * w2.z + q3 * w3.z;
        r.w = bb.w + q0 * w0.w + q1 * w1.w + q2 * w2.w + q3 * w3.w;
        o[j] = r;
    }
}

// ---------------------------------------------------------------------------
extern "C" void kernel_launch(void* const* d_in, const int* in_sizes, int n_in,
                              void* d_out, int out_size) {
    const float* inputs = (const float*)d_in[0];
    const float* W1     = (const float*)d_in[1];
    const float* b1     = (const float*)d_in[2];
    const float* qw     = (const float*)d_in[3];
    const float* W2     = (const float*)d_in[4];
    const float* b2     = (const float*)d_in[5];

    setup_kernel<<<1, 32>>>(qw);
    angle_kernel<<<BATCH / 8, 256>>>(inputs, (const float4*)W1, b1);
    tail_kernel<<<BATCH / 256, 256>>>((const float4*)W2, (const float4*)b2,
                                      (float4*)d_out);
}

// round 2
// speedup vs baseline: 1.1158x; 1.1158x over previous
#include <cuda_runtime.h>

#define BATCH   262144
#define IN_DIM  768
#define OUT_DIM 32
#define QDEPTH  6

// ---------------------------------------------------------------------------
// One fused kernel.
//  - Block: 256 threads = 8 warps; each warp handles 4 samples -> 32/block.
//  - Warp 7 lanes 0-15 additionally compose the fixed circuit (CNOT+RY(qw))
//    into a 16x16 matrix M in shared (redundant per block, hidden by loads).
//  - GEMV: warp-per-sample-group, LDG.128 inputs, LDS.128 transposed W1.
//  - Tail: lane-parallel M@s, signed butterfly, 32-lane output row write.
// Index convention (matches JAX ref): state index i = q0*8+q1*4+q2*2+q3.
// ---------------------------------------------------------------------------
__global__ __launch_bounds__(256) void fused_kernel(
    const float*  __restrict__ inp,
    const float4* __restrict__ w1v,   // W1 [768][4] as 768 float4
    const float*  __restrict__ b1,
    const float*  __restrict__ qw,    // [6][4]
    const float*  __restrict__ w2,    // [4][32]
    const float*  __restrict__ b2,    // [32]
    float*        __restrict__ out)
{
    __shared__ float4 swv[4][IN_DIM / 4];  // swv[d][g] = W1[4g..4g+3][d]
    __shared__ float  sM[256];             // sM[j*16+i] = M[i][j]
    __shared__ float  sW2[128];            // [w*32+j]
    __shared__ float  sb2[32];
    __shared__ float  sb1[4];

    const int tid  = threadIdx.x;
    const int lane = tid & 31;
    const int warp = tid >> 5;

    // ---- cooperative constant loads / transpose ----
    if (tid < 192) {
        float4 a = w1v[4 * tid], b = w1v[4 * tid + 1];
        float4 c = w1v[4 * tid + 2], d = w1v[4 * tid + 3];
        swv[0][tid] = make_float4(a.x, b.x, c.x, d.x);
        swv[1][tid] = make_float4(a.y, b.y, c.y, d.y);
        swv[2][tid] = make_float4(a.z, b.z, c.z, d.z);
        swv[3][tid] = make_float4(a.w, b.w, c.w, d.w);
    }
    if (tid < 128) sW2[tid] = w2[tid];
    if (tid < 32)  sb2[tid] = b2[tid];
    if (tid < 4)   sb1[tid] = b1[tid];

    // ---- warp 7: build fixed-circuit matrix M (column j per lane) ----
    if (tid >= 224 && tid < 240) {
        const int j = tid - 224;
        float v[16];
#pragma unroll
        for (int i = 0; i < 16; i++) v[i] = (i == j) ? 1.0f : 0.0f;
        const int cm[3] = {8, 2, 4};
        const int tm[3] = {4, 1, 2};
        for (int k = 0; k < QDEPTH; k++) {
#pragma unroll
            for (int g = 0; g < 3; g++) {
                int cmask = cm[g], tmask = tm[g];
#pragma unroll
                for (int i = 0; i < 16; i++)
                    if ((i & cmask) && !(i & tmask)) {
                        float t = v[i]; v[i] = v[i | tmask]; v[i | tmask] = t;
                    }
            }
#pragma unroll
            for (int w = 0; w < 4; w++) {
                int mask = 8 >> w;
                float s, c;
                __sincosf(0.5f * qw[k * 4 + w], &s, &c);
#pragma unroll
                for (int i = 0; i < 16; i++)
                    if (!(i & mask)) {
                        float a0 = v[i], a1 = v[i | mask];
                        v[i]        = c * a0 - s * a1;
                        v[i | mask] = s * a0 + c * a1;
                    }
            }
        }
#pragma unroll
        for (int i = 0; i < 16; i++) sM[j * 16 + i] = v[i];
    }
    __syncthreads();

    // ---- GEMV: 4 samples per warp, LDG.128 ----
    const long s0 = ((long)blockIdx.x * 8 + warp) * 4;
    const float4* r0 = (const float4*)inp + (s0 + 0) * (IN_DIM / 4);
    const float4* r1 = (const float4*)inp + (s0 + 1) * (IN_DIM / 4);
    const float4* r2 = (const float4*)inp + (s0 + 2) * (IN_DIM / 4);
    const float4* r3 = (const float4*)inp + (s0 + 3) * (IN_DIM / 4);

    float acc[4][4];
#pragma unroll
    for (int k = 0; k < 4; k++)
#pragma unroll
        for (int d = 0; d < 4; d++) acc[k][d] = 0.0f;

#pragma unroll
    for (int it = 0; it < IN_DIM / 128; it++) {
        int idx = it * 32 + lane;
        float4 x0 = r0[idx], x1 = r1[idx], x2 = r2[idx], x3 = r3[idx];
        float4 w0 = swv[0][idx], w1 = swv[1][idx];
        float4 w2s = swv[2][idx], w3 = swv[3][idx];
#define DOT(K, X)                                                        \
        acc[K][0] = fmaf(X.x, w0.x, fmaf(X.y, w0.y, fmaf(X.z, w0.z, fmaf(X.w, w0.w, acc[K][0])))); \
        acc[K][1] = fmaf(X.x, w1.x, fmaf(X.y, w1.y, fmaf(X.z, w1.z, fmaf(X.w, w1.w, acc[K][1])))); \
        acc[K][2] = fmaf(X.x, w2s.x, fmaf(X.y, w2s.y, fmaf(X.z, w2s.z, fmaf(X.w, w2s.w, acc[K][2])))); \
        acc[K][3] = fmaf(X.x, w3.x, fmaf(X.y, w3.y, fmaf(X.z, w3.z, fmaf(X.w, w3.w, acc[K][3]))));
        DOT(0, x0) DOT(1, x1) DOT(2, x2) DOT(3, x3)
#undef DOT
    }

    // ---- butterfly: every lane ends with all 16 (k,d) sums ----
#pragma unroll
    for (int k = 0; k < 4; k++)
#pragma unroll
        for (int d = 0; d < 4; d++)
#pragma unroll
            for (int off = 16; off; off >>= 1)
                acc[k][d] += __shfl_xor_sync(0xffffffffu, acc[k][d], off);

    // ---- angles: lane L(<16, duplicated on 16-31) -> tanh for (k=L>>2,d=L&3)
    const int lm = lane & 15;
    float sel = acc[0][0];
#pragma unroll
    for (int k = 0; k < 4; k++)
#pragma unroll
        for (int d = 0; d < 4; d++)
            if (lm == k * 4 + d) sel = acc[k][d];
    const float PI4 = 0.78539816339744830962f;
    float th = tanhf(sel + sb1[lm & 3]) * PI4 + PI4;

    // ---- per-lane row of M (lane i -> M[i][*]) ----
    float Mrow[16];
#pragma unroll
    for (int j = 0; j < 16; j++) Mrow[j] = sM[j * 16 + lm];

    // ---- tails: 4 samples sequentially ----
#pragma unroll
    for (int k = 0; k < 4; k++) {
        float t0 = __shfl_sync(0xffffffffu, th, 4 * k + 0);
        float t1 = __shfl_sync(0xffffffffu, th, 4 * k + 1);
        float t2 = __shfl_sync(0xffffffffu, th, 4 * k + 2);
        float t3 = __shfl_sync(0xffffffffu, th, 4 * k + 3);
        float s0_, c0_, s1_, c1_, s2_, c2_, s3_, c3_;
        __sincosf(t0, &s0_, &c0_);
        __sincosf(t1, &s1_, &c1_);
        __sincosf(t2, &s2_, &c2_);
        __sincosf(t3, &s3_, &c3_);

        float A[4]  = {c0_ * c1_, c0_ * s1_, s0_ * c1_, s0_ * s1_};
        float Bq[4] = {c2_ * c3_, c2_ * s3_, s2_ * c3_, s2_ * s3_};
        float sv[16];
#pragma unroll
        for (int i = 0; i < 16; i++) sv[i] = A[i >> 2] * Bq[i & 3];

        float t = 0.0f;
#pragma unroll
        for (int j = 0; j < 16; j++) t = fmaf(Mrow[j], sv[j], t);

        float p = (lane < 16) ? t * t : 0.0f;
        float rr0 = (lane & 8) ? -p : p;
        float rr1 = (lane & 4) ? -p : p;
        float rr2 = (lane & 2) ? -p : p;
        float rr3 = (lane & 1) ? -p : p;
#pragma unroll
        for (int off = 16; off; off >>= 1) {
            rr0 += __shfl_xor_sync(0xffffffffu, rr0, off);
            rr1 += __shfl_xor_sync(0xffffffffu, rr1, off);
            rr2 += __shfl_xor_sync(0xffffffffu, rr2, off);
            rr3 += __shfl_xor_sync(0xffffffffu, rr3, off);
        }

        float o = sb2[lane]
                + rr0 * sW2[lane]       + rr1 * sW2[32 + lane]
                + rr2 * sW2[64 + lane]  + rr3 * sW2[96 + lane];
        out[(s0 + k) * OUT_DIM + lane] = o;
    }
}

// ---------------------------------------------------------------------------
extern "C" void kernel_launch(void* const* d_in, const int* in_sizes, int n_in,
                              void* d_out, int out_size) {
    const float* inputs = (const float*)d_in[0];
    const float* W1     = (const float*)d_in[1];
    const float* b1     = (const float*)d_in[2];
    const float* qw     = (const float*)d_in[3];
    const float* W2     = (const float*)d_in[4];
    const float* b2     = (const float*)d_in[5];

    fused_kernel<<<BATCH / 32, 256>>>(inputs, (const float4*)W1, b1, qw, W2, b2,
                                      (float*)d_out);
}